// round 1
// baseline (speedup 1.0000x reference)
#include <cuda_runtime.h>
#include <cstdint>
#include <cstddef>

// BioConvolution: 256 independent GEMMs  C_l[64,128] = A_l[64,1024] * B_l[1024,128]
//   A_l[m][k]  = X[m, r*4+i, c*4+j, ch]   (k = i*256 + j*64 + ch, l = r*16+c)
//   B_l[k][f]  = filters[l*131072 + k*128 + f]
//   out[(m*256+l)*128 + f] = relu(C + bias[f])

namespace {

constexpr int M_DIM   = 64;    // batch
constexpr int NF      = 128;   // fout
constexpr int KTOT    = 1024;
constexpr int BK      = 64;
constexpr int ASTRIDE = 68;    // 64 + 4 pad (keeps 16B alignment: 68*4=272)
constexpr int NCHUNK  = KTOT / BK;  // 16
constexpr int SMEM_BYTES = (2 * M_DIM * ASTRIDE + 2 * BK * NF) * 4; // 100,352 B

__device__ __forceinline__ uint32_t smem_u32(const void* p) {
    return static_cast<uint32_t>(__cvta_generic_to_shared(p));
}
__device__ __forceinline__ void cp16(uint32_t s, const float* g) {
    asm volatile("cp.async.cg.shared.global [%0], [%1], 16;" :: "r"(s), "l"(g));
}
__device__ __forceinline__ void cp_commit() {
    asm volatile("cp.async.commit_group;");
}
template <int N>
__device__ __forceinline__ void cp_wait() {
    asm volatile("cp.async.wait_group %0;" :: "n"(N));
}

// packed f32x2 helpers (FFMA2 path: 2 FMAs per instruction)
__device__ __forceinline__ unsigned long long splat2(float a) {
    unsigned long long r;
    asm volatile("mov.b64 %0, {%1, %1};" : "=l"(r) : "f"(a));
    return r;
}
__device__ __forceinline__ void fma2(unsigned long long& c,
                                     unsigned long long a,
                                     unsigned long long b) {
    asm volatile("fma.rn.f32x2 %0, %1, %2, %0;" : "+l"(c) : "l"(a), "l"(b));
}
__device__ __forceinline__ float2 unpack2(unsigned long long v) {
    float2 f;
    asm volatile("mov.b64 {%0, %1}, %2;" : "=f"(f.x), "=f"(f.y) : "l"(v));
    return f;
}

__global__ __launch_bounds__(256, 2)
void bioconv_kernel(const float* __restrict__ X,
                    const float* __restrict__ filt,
                    const float* __restrict__ bias,
                    float* __restrict__ out) {
    extern __shared__ __align__(16) float smem[];
    float* As = smem;                        // [2][64][ASTRIDE]
    float* Bs = smem + 2 * M_DIM * ASTRIDE;  // [2][BK][NF]

    const int tid = threadIdx.x;
    const int l   = blockIdx.x;
    const int r   = l >> 4;
    const int c   = l & 15;

    // ---- loader mapping ----
    // A: 64 rows (m) x 64 ch per chunk; 4 threads per row, each 4x float4
    const int am = tid >> 2;     // 0..63
    const int aq = tid & 3;      // 0..3
    const float* gA0 = X + (size_t)(am * 64 + r * 4) * 4096 + (size_t)(c * 4) * 64;
    const float* gB0 = filt + (size_t)l * (KTOT * NF);

    // ---- compute mapping: 16x16 thread grid, 4(M) x 8(N) microtile ----
    const int tn = tid & 15;
    const int tm = tid >> 4;
    const int n0 = tn * 8;
    const int m0 = tm * 4;

    unsigned long long acc[4][4];
#pragma unroll
    for (int i = 0; i < 4; ++i)
#pragma unroll
        for (int j = 0; j < 4; ++j) acc[i][j] = 0ull;

    auto load_chunk = [&](int t, int stage) {
        const int ii = t >> 2, jj = t & 3;
        const float* ga = gA0 + ii * 4096 + jj * 64;
        float* sa = As + (size_t)(stage * M_DIM + am) * ASTRIDE;
#pragma unroll
        for (int v = 0; v < 4; ++v) {
            const int ch = v * 16 + aq * 4;
            cp16(smem_u32(sa + ch), ga + ch);
        }
        const float* gb = gB0 + (size_t)t * BK * NF;
        float* sb = Bs + (size_t)stage * (BK * NF);
#pragma unroll
        for (int it = 0; it < 8; ++it) {
            const int off = (it * 256 + tid) * 4;
            cp16(smem_u32(sb + off), gb + off);
        }
    };

    load_chunk(0, 0);
    cp_commit();

    for (int t = 0; t < NCHUNK; ++t) {
        const int stage = t & 1;
        if (t + 1 < NCHUNK) {
            load_chunk(t + 1, stage ^ 1);
            cp_commit();
            cp_wait<1>();
        } else {
            cp_wait<0>();
        }
        __syncthreads();

        const float* a_base = As + (size_t)(stage * M_DIM + m0) * ASTRIDE;
        const float* b_base = Bs + (size_t)stage * (BK * NF) + n0;

#pragma unroll 4
        for (int kk = 0; kk < BK; ++kk) {
            const ulonglong2 b01 =
                *reinterpret_cast<const ulonglong2*>(b_base + (size_t)kk * NF);
            const ulonglong2 b23 =
                *reinterpret_cast<const ulonglong2*>(b_base + (size_t)kk * NF + 4);
            unsigned long long bb0 = b01.x, bb1 = b01.y, bb2 = b23.x, bb3 = b23.y;
#pragma unroll
            for (int mi = 0; mi < 4; ++mi) {
                const unsigned long long av = splat2(a_base[mi * ASTRIDE + kk]);
                fma2(acc[mi][0], av, bb0);
                fma2(acc[mi][1], av, bb1);
                fma2(acc[mi][2], av, bb2);
                fma2(acc[mi][3], av, bb3);
            }
        }
        __syncthreads();
    }

    // ---- epilogue: bias + relu, vectorized store ----
    float bv[8];
#pragma unroll
    for (int j = 0; j < 8; ++j) bv[j] = bias[n0 + j];

#pragma unroll
    for (int mi = 0; mi < 4; ++mi) {
        const int m = m0 + mi;
        float* op = out + ((size_t)m * 256 + l) * NF + n0;
        float vals[8];
#pragma unroll
        for (int nj = 0; nj < 4; ++nj) {
            const float2 v = unpack2(acc[mi][nj]);
            vals[nj * 2]     = v.x;
            vals[nj * 2 + 1] = v.y;
        }
        float4 o0, o1;
        o0.x = fmaxf(vals[0] + bv[0], 0.f);
        o0.y = fmaxf(vals[1] + bv[1], 0.f);
        o0.z = fmaxf(vals[2] + bv[2], 0.f);
        o0.w = fmaxf(vals[3] + bv[3], 0.f);
        o1.x = fmaxf(vals[4] + bv[4], 0.f);
        o1.y = fmaxf(vals[5] + bv[5], 0.f);
        o1.z = fmaxf(vals[6] + bv[6], 0.f);
        o1.w = fmaxf(vals[7] + bv[7], 0.f);
        *reinterpret_cast<float4*>(op)     = o0;
        *reinterpret_cast<float4*>(op + 4) = o1;
    }
}

}  // namespace

extern "C" void kernel_launch(void* const* d_in, const int* in_sizes, int n_in,
                              void* d_out, int out_size) {
    const float* X    = (const float*)d_in[0];
    const float* filt = (const float*)d_in[1];
    const float* bias = (const float*)d_in[2];
    float* out        = (float*)d_out;

    cudaFuncSetAttribute(bioconv_kernel,
                         cudaFuncAttributeMaxDynamicSharedMemorySize, SMEM_BYTES);
    bioconv_kernel<<<256, 256, SMEM_BYTES>>>(X, filt, bias, out);
}

// round 3
// speedup vs baseline: 3.2351x; 3.2351x over previous
#include <cuda_runtime.h>
#include <cstdint>
#include <cstddef>

// BioConvolution: 256 independent GEMMs  C_l[64,128] = A_l[64,1024] * B_l[1024,128]
//   A_l[m][k] = X[m, r*4+i, c*4+j, ch]  (k = i*256+j*64+ch, l = r*16+c)
//   B_l[k][f] = filters[l*131072 + k*128 + f]
//   out[(m*256+l)*128+f] = relu(C + bias[f])
//
// Tensor-core path via sm_80-portable mma.sync m16n8k8 tf32 (the harness lowers
// PTX to .target sm_103 without the 'a' suffix, so tcgen05 is unavailable).
// One CTA per l: 256 threads = 8 warps in 2(M)x4(N) grid, warp tile 32x32,
// K streamed in 32-float chunks through a 3-stage cp.async ring.

namespace {

constexpr int NST  = 32;            // K chunks (1024/32)
constexpr int AS   = 36;            // A smem row stride (floats): banks (4g+t)%32 distinct
constexpr int BSTR = 132;           // B smem row stride (floats): banks (4t+g)%32 distinct
constexpr int TILE_A = 64 * AS;     // 2304 floats
constexpr int TILE_B = 32 * BSTR;   // 4224 floats
constexpr int STAGE  = TILE_A + TILE_B;      // 6528 floats
constexpr int SMEM_BYTES = 3 * STAGE * 4;    // 78336 B -> 2 CTAs/SM

__device__ __forceinline__ uint32_t smem_u32(const void* p) {
    return static_cast<uint32_t>(__cvta_generic_to_shared(p));
}
__device__ __forceinline__ void cp16(uint32_t s, const float* g) {
    asm volatile("cp.async.cg.shared.global [%0], [%1], 16;" :: "r"(s), "l"(g));
}
__device__ __forceinline__ void cp_commit() {
    asm volatile("cp.async.commit_group;");
}
template <int N>
__device__ __forceinline__ void cp_wait() {
    asm volatile("cp.async.wait_group %0;" :: "n"(N));
}
__device__ __forceinline__ uint32_t f2tf32(float f) {
    uint32_t r;
    asm("cvt.rna.tf32.f32 %0, %1;" : "=r"(r) : "f"(f));
    return r;
}
__device__ __forceinline__ void mma_tf32(float* c, const uint32_t* a, const uint32_t* b) {
    asm volatile(
        "mma.sync.aligned.m16n8k8.row.col.f32.tf32.tf32.f32 "
        "{%0,%1,%2,%3}, {%4,%5,%6,%7}, {%8,%9}, {%0,%1,%2,%3};"
        : "+f"(c[0]), "+f"(c[1]), "+f"(c[2]), "+f"(c[3])
        : "r"(a[0]), "r"(a[1]), "r"(a[2]), "r"(a[3]), "r"(b[0]), "r"(b[1]));
}

__global__ __launch_bounds__(256, 2)
void bioconv_mma_kernel(const float* __restrict__ X,
                        const float* __restrict__ filt,
                        const float* __restrict__ bias,
                        float* __restrict__ out) {
    extern __shared__ __align__(16) float smem[];

    const int tid = threadIdx.x;
    const int l   = blockIdx.x;
    const int r   = l >> 4;
    const int cc  = l & 15;

    // ---------------- loader mapping ----------------
    // A: 64 rows x 32 floats (128B = 8 cp16) per stage -> 512 cp16 -> 2/thread
    // B: 32 rows x 128 floats (512B = 32 cp16) per stage -> 1024 cp16 -> 4/thread
    const int a_m0  = tid >> 3;            // rows tid>>3 and (tid+256)>>3
    const int a_c0  = tid & 7;             // 16B chunk within 128B row
    const float* gAbase = X + (size_t)r * 16384 + (size_t)cc * 256;
    const float* gB     = filt + (size_t)l * 131072;

    // ---------------- compute mapping ----------------
    const int lane = tid & 31;
    const int wid  = tid >> 5;
    const int wm   = wid >> 2;             // 0..1 -> m offset wm*32
    const int wn   = wid & 3;              // 0..3 -> n offset wn*32
    const int g    = lane >> 2;            // groupID 0..7
    const int t4   = lane & 3;             // threadID in group

    float acc[2][4][4];
#pragma unroll
    for (int i = 0; i < 2; ++i)
#pragma unroll
        for (int j = 0; j < 4; ++j)
#pragma unroll
            for (int k = 0; k < 4; ++k) acc[i][j][k] = 0.f;

    auto load_stage = [&](int t, int s) {
        const int i = t >> 3, j = (t >> 1) & 3, half = (t & 1) << 5;
        float* As = smem + (size_t)s * STAGE;
        float* Bs = As + TILE_A;
        const float* ga = gAbase + i * 4096 + j * 64 + half;
#pragma unroll
        for (int v = 0; v < 2; ++v) {
            const int m = a_m0 + v * 32;
            cp16(smem_u32(As + m * AS + a_c0 * 4),
                 ga + (size_t)m * 262144 + a_c0 * 4);
        }
        const float* gb = gB + (size_t)t * 4096;
#pragma unroll
        for (int v = 0; v < 4; ++v) {
            const int idx = tid + v * 256;
            const int kr = idx >> 5, n16 = idx & 31;
            cp16(smem_u32(Bs + kr * BSTR + n16 * 4), gb + kr * 128 + n16 * 4);
        }
        cp_commit();
    };

    load_stage(0, 0);
    load_stage(1, 1);

    for (int t = 0; t < NST; ++t) {
        const int s = t % 3;
        if (t + 1 < NST) cp_wait<1>(); else cp_wait<0>();
        __syncthreads();

        const float* As = smem + (size_t)s * STAGE;
        const float* Bs = As + TILE_A;
        const float* a_row0 = As + (wm * 32 + g) * AS + t4;
        const float* b_row0 = Bs + t4 * BSTR + wn * 32 + g;

#pragma unroll
        for (int k8 = 0; k8 < 4; ++k8) {
            uint32_t af[2][4];
#pragma unroll
            for (int mt = 0; mt < 2; ++mt) {
                const float* ap = a_row0 + mt * 16 * AS + k8 * 8;
                af[mt][0] = f2tf32(ap[0]);
                af[mt][1] = f2tf32(ap[8 * AS]);
                af[mt][2] = f2tf32(ap[4]);
                af[mt][3] = f2tf32(ap[8 * AS + 4]);
            }
            uint32_t bf[4][2];
#pragma unroll
            for (int nt = 0; nt < 4; ++nt) {
                const float* bp = b_row0 + k8 * 8 * BSTR + nt * 8;
                bf[nt][0] = f2tf32(bp[0]);
                bf[nt][1] = f2tf32(bp[4 * BSTR]);
            }
#pragma unroll
            for (int mt = 0; mt < 2; ++mt)
#pragma unroll
                for (int nt = 0; nt < 4; ++nt)
                    mma_tf32(acc[mt][nt], af[mt], bf[nt]);
        }
        __syncthreads();
        if (t + 2 < NST) load_stage(t + 2, (t + 2) % 3);
    }

    // ---------------- epilogue: bias + relu ----------------
#pragma unroll
    for (int nt = 0; nt < 4; ++nt) {
        const int n0 = wn * 32 + nt * 8 + t4 * 2;
        const float2 bv = *reinterpret_cast<const float2*>(bias + n0);
#pragma unroll
        for (int mt = 0; mt < 2; ++mt) {
            const int m = wm * 32 + mt * 16 + g;
            float2 o0, o1;
            o0.x = fmaxf(acc[mt][nt][0] + bv.x, 0.f);
            o0.y = fmaxf(acc[mt][nt][1] + bv.y, 0.f);
            o1.x = fmaxf(acc[mt][nt][2] + bv.x, 0.f);
            o1.y = fmaxf(acc[mt][nt][3] + bv.y, 0.f);
            *reinterpret_cast<float2*>(out + ((size_t)m * 256 + l) * 128 + n0) = o0;
            *reinterpret_cast<float2*>(out + ((size_t)(m + 8) * 256 + l) * 128 + n0) = o1;
        }
    }
}

}  // namespace

extern "C" void kernel_launch(void* const* d_in, const int* in_sizes, int n_in,
                              void* d_out, int out_size) {
    const float* X    = (const float*)d_in[0];
    const float* filt = (const float*)d_in[1];
    const float* bias = (const float*)d_in[2];
    float* out        = (float*)d_out;

    cudaFuncSetAttribute(bioconv_mma_kernel,
                         cudaFuncAttributeMaxDynamicSharedMemorySize, SMEM_BYTES);
    bioconv_mma_kernel<<<256, 256, SMEM_BYTES>>>(X, filt, bias, out);
}